// round 7
// baseline (speedup 1.0000x reference)
#include <cuda_runtime.h>
#include <math.h>
#include <float.h>

#define Bv 2
#define Nv 4096
#define Cv 64
#define TOPKv 24
#define MAXM 512

// Output layout (concatenated, float32):
// expected (B,N,3) | disp (B,3,N) | probs (B,N,N) | conf (B,N) | ent (B,N) | src_pos (B,N,3)
#define EXP_OFF   ((size_t)0)
#define DISP_OFF  ((size_t)(Bv*Nv*3))
#define PROBS_OFF ((size_t)(2*Bv*Nv*3))
#define CONF_OFF  (PROBS_OFF + (size_t)Bv*Nv*Nv)
#define ENT_OFF   (CONF_OFF + (size_t)Bv*Nv)
#define SP_OFF    (ENT_OFF + (size_t)Bv*Nv)

// Scratch (no cudaMalloc allowed)
__device__ float4 g_pack[Bv*Nv];            // (x, y, z, ||t||^2) per target node
__device__ float  g_tdT[(size_t)Bv*Nv*Cv];  // tgt_desc transposed: (B,N,64)
__device__ float  g_adj[Bv*Nv];             // max(log softmax(tml)[...,0], -20) - 0.1*tgt_unc

__global__ void prep_kernel(const float* __restrict__ td,
                            const float* __restrict__ tc,
                            const float* __restrict__ tml,
                            const float* __restrict__ tunc) {
    int idx = blockIdx.x * blockDim.x + threadIdx.x;
    if (idx < Bv * Cv * Nv) {
        int b = idx / (Cv * Nv);
        int r = idx - b * (Cv * Nv);
        int c = r / Nv;
        int j = r - c * Nv;
        g_tdT[(((size_t)b * Nv + j) << 6) + c] = td[idx];
    }
    if (idx < Bv * Nv) {
        int b = idx >> 12, j = idx & (Nv - 1);
        const float* t = tc + (size_t)b * 3 * Nv;
        float x = t[j], y = t[Nv + j], z = t[2 * Nv + j];
        g_pack[idx] = make_float4(x, y, z, x * x + y * y + z * z);
        float l0 = tml[(size_t)b * 2 * Nv + j];
        float l1 = tml[(size_t)b * 2 * Nv + Nv + j];
        // log(softmax[...,0]) = -log1p(exp(l1-l0)); overflow -> -inf -> clamped to -20
        g_adj[idx] = fmaxf(-log1pf(expf(l1 - l0)), -20.0f) - 0.1f * tunc[idx];
    }
}

__global__ void __launch_bounds__(256)
matcher_kernel(const float* __restrict__ src_can,
               const float* __restrict__ src_desc,
               const float* __restrict__ src_ml,
               const float* __restrict__ src_unc,
               float* __restrict__ out) {
    __shared__ float4 s_row4[Nv / 4];     // 16 KB staged probs row
    __shared__ float  s_sd[64];
    __shared__ int    s_idx[MAXM];
    __shared__ float  s_d2a[MAXM];
    __shared__ float  s_val[MAXM];
    __shared__ float  s_red[64];          // fused reduction buffer
    __shared__ int    s_redi[8];
    __shared__ int    s_cnt;

    const int tid  = threadIdx.x;
    const int lane = tid & 31;
    const int bi   = blockIdx.x;
    const int b    = bi >> 12;
    const int i    = bi & (Nv - 1);
    const int bN   = b * Nv;

    // Zero the staged probs row in smem
    float* s_row = reinterpret_cast<float*>(s_row4);
#pragma unroll
    for (int k = 0; k < 4; k++) s_row4[tid + 256 * k] = make_float4(0.f, 0.f, 0.f, 0.f);

    if (tid < 64) s_sd[tid] = src_desc[((size_t)b * 64 + tid) * Nv + i];
    if (tid == 0) s_cnt = 0;

    const float* sc = src_can + (size_t)b * 3 * Nv;
    const float sx = sc[i], sy = sc[Nv + i], sz = sc[2 * Nv + i];
    const float sn2 = sx * sx + sy * sy + sz * sz;
    const float sunc = src_unc[bN + i];

    __syncthreads();   // s_cnt init + s_sd visible

    const float4* __restrict__ pk = g_pack + bN;
    const float R2 = 0.45f * 0.45f;

    // Distances + inline gather of radius-allowed pairs (fast path)
#pragma unroll
    for (int k = 0; k < 16; k++) {
        int j = (k << 8) + tid;
        float4 t = pk[j];
        float dot = fmaf(sx, t.x, fmaf(sy, t.y, sz * t.z));
        float d2  = fmaf(-2.0f, dot, sn2 + t.w);
        if (d2 <= R2) {
            int p = atomicAdd(&s_cnt, 1);
            if (p < MAXM) { s_idx[p] = j; s_d2a[p] = d2; }
        }
    }
    __syncthreads();
    int M = s_cnt;

    if (M < TOPKv) {
        // Rare slow path (~3% of rows): extend tau to the TOPK-th smallest d2.
        // All control state (tau, ctot) is block-uniform; shuffles converged.
        float tau = R2;
        int ctot = M;
        while (ctot < TOPKv) {
            float m = FLT_MAX; int c = 0;
#pragma unroll
            for (int k = 0; k < 16; k++) {
                int j = (k << 8) + tid;
                float4 t = pk[j];
                float dot = fmaf(sx, t.x, fmaf(sy, t.y, sz * t.z));
                float d2  = fmaf(-2.0f, dot, sn2 + t.w);
                if (d2 > tau) {
                    if (d2 < m) { m = d2; c = 1; }
                    else if (d2 == m) c++;
                }
            }
            // fused (min, tie-count) block reduction
#pragma unroll
            for (int o = 16; o; o >>= 1) {
                float om = __shfl_xor_sync(0xffffffffu, m, o);
                int   oc = __shfl_xor_sync(0xffffffffu, c, o);
                if (om < m) { m = om; c = oc; }
                else if (om == m) c += oc;
            }
            if (lane == 0) { s_red[tid >> 5] = m; s_redi[tid >> 5] = c; }
            __syncthreads();
            if (tid == 0) {
                float mm = s_red[0]; int cc = s_redi[0];
#pragma unroll
                for (int w = 1; w < 8; w++) {
                    if (s_red[w] < mm) { mm = s_red[w]; cc = s_redi[w]; }
                    else if (s_red[w] == mm) cc += s_redi[w];
                }
                s_red[0] = mm; s_redi[0] = cc;
            }
            __syncthreads();
            m = s_red[0]; c = s_redi[0];
            __syncthreads();
            if (m >= FLT_MAX) break;
            tau = m; ctot += c;
        }
        // gather the extras in (R2, tau]
#pragma unroll
        for (int k = 0; k < 16; k++) {
            int j = (k << 8) + tid;
            float4 t = pk[j];
            float dot = fmaf(sx, t.x, fmaf(sy, t.y, sz * t.z));
            float d2  = fmaf(-2.0f, dot, sn2 + t.w);
            if (d2 > R2 && d2 <= tau) {
                int p = atomicAdd(&s_cnt, 1);
                if (p < MAXM) { s_idx[p] = j; s_d2a[p] = d2; }
            }
        }
        __syncthreads();
        M = s_cnt;
    }
    M = min(M, MAXM);

    // Scores for allowed pairs: half-warp (16 lanes) per pair, 64-dim dot.
    // BLOCK-UNIFORM trip count so every lane of every warp executes every
    // shuffle (round-6 deadlock fix); out-of-range p contributes zero work.
    {
        const int half = tid >> 4;        // 0..15
        const int hl   = tid & 15;
        const float4 sd4 = reinterpret_cast<const float4*>(s_sd)[hl];
        const int T = (M + 15) >> 4;
        for (int t = 0; t < T; t++) {
            int p = (t << 4) + half;
            float part = 0.0f;
            int j = 0;
            if (p < M) {
                j = s_idx[p];
                const float4* tdj4 =
                    reinterpret_cast<const float4*>(g_tdT + ((size_t)(bN + j) << 6));
                float4 v = tdj4[hl];   // one LDG.128 per lane
                part = fmaf(v.x, sd4.x, fmaf(v.y, sd4.y,
                       fmaf(v.z, sd4.z, v.w * sd4.w)));
            }
#pragma unroll
            for (int o = 8; o; o >>= 1)
                part += __shfl_xor_sync(0xffffffffu, part, o, 16);
            if (hl == 0 && p < M) {
                float dist = sqrtf(fmaxf(s_d2a[p], 1e-12f));
                s_val[p] = part - dist - 0.1f * sunc + g_adj[bN + j];
            }
        }
    }
    __syncthreads();

    // Softmax over sparse allowed set (disallowed entries underflow to exact 0
    // in the reference too: exp(-1e4/0.07) == 0 in fp32)
    // Round 1: block max
    float lm = -FLT_MAX;
    for (int p = tid; p < M; p += 256) lm = fmaxf(lm, s_val[p]);
#pragma unroll
    for (int o = 16; o; o >>= 1) lm = fmaxf(lm, __shfl_xor_sync(0xffffffffu, lm, o));
    if (lane == 0) s_red[56 + (tid >> 5)] = lm;
    __syncthreads();
    float mx = s_red[56];
#pragma unroll
    for (int w = 1; w < 8; w++) mx = fmaxf(mx, s_red[56 + w]);

    // Round 2: fused sums (Z, eu, e0, e1, e2) + max (em)
    const float invT = 1.0f / 0.07f;
    const float step = 2.0f / 15.0f;
    float Z = 0.f, eu = 0.f, e0 = 0.f, e1 = 0.f, e2 = 0.f, em = 0.f;
    for (int p = tid; p < M; p += 256) {
        float u = (s_val[p] - mx) * invT;
        float e = __expf(u);
        s_val[p] = e;
        Z += e; eu += e * u; em = fmaxf(em, e);
        int j = s_idx[p];
        float c0 = (float)(j >> 8) * step - 1.0f;
        float c1 = (float)((j >> 4) & 15) * step - 1.0f;
        float c2 = (float)(j & 15) * step - 1.0f;
        e0 += e * c0; e1 += e * c1; e2 += e * c2;
    }
#pragma unroll
    for (int o = 16; o; o >>= 1) {
        Z  += __shfl_xor_sync(0xffffffffu, Z, o);
        eu += __shfl_xor_sync(0xffffffffu, eu, o);
        e0 += __shfl_xor_sync(0xffffffffu, e0, o);
        e1 += __shfl_xor_sync(0xffffffffu, e1, o);
        e2 += __shfl_xor_sync(0xffffffffu, e2, o);
        em  = fmaxf(em, __shfl_xor_sync(0xffffffffu, em, o));
    }
    if (lane == 0) {
        int base = (tid >> 5) * 6;                  // [0..47], disjoint from [56..63]
        s_red[base + 0] = Z;  s_red[base + 1] = eu; s_red[base + 2] = e0;
        s_red[base + 3] = e1; s_red[base + 4] = e2; s_red[base + 5] = em;
    }
    __syncthreads();
    // lanes 0..5 of every warp each reduce one quantity over the 8 warps
    float acc = 0.f;
    if (lane < 5) {
#pragma unroll
        for (int w = 0; w < 8; w++) acc += s_red[w * 6 + lane];
    } else if (lane == 5) {
        acc = s_red[5];
#pragma unroll
        for (int w = 1; w < 8; w++) acc = fmaxf(acc, s_red[w * 6 + 5]);
    }
    float rZ  = __shfl_sync(0xffffffffu, acc, 0);
    float reu = __shfl_sync(0xffffffffu, acc, 1);
    float re0 = __shfl_sync(0xffffffffu, acc, 2);
    float re1 = __shfl_sync(0xffffffffu, acc, 3);
    float re2 = __shfl_sync(0xffffffffu, acc, 4);
    float rem = __shfl_sync(0xffffffffu, acc, 5);

    float invZ = 1.0f / rZ;

    // Scatter normalized probs into the smem row, then coalesced copy-out
    for (int p = tid; p < M; p += 256) s_row[s_idx[p]] = s_val[p] * invZ;
    __syncthreads();

    float4* rowp = reinterpret_cast<float4*>(out + PROBS_OFF + (size_t)(bN + i) * Nv);
#pragma unroll
    for (int k = 0; k < 4; k++) rowp[tid + 256 * k] = s_row4[tid + 256 * k];

    if (tid == 0) {
        float Ex0 = re0 * invZ, Ex1 = re1 * invZ, Ex2 = re2 * invZ;
        float p0 = (float)(i >> 8) * step - 1.0f;
        float p1 = (float)((i >> 4) & 15) * step - 1.0f;
        float p2 = (float)(i & 15) * step - 1.0f;
        size_t ri = (size_t)(bN + i);
        out[EXP_OFF + ri * 3 + 0] = Ex0;
        out[EXP_OFF + ri * 3 + 1] = Ex1;
        out[EXP_OFF + ri * 3 + 2] = Ex2;
        out[DISP_OFF + (size_t)b * 3 * Nv + 0 * Nv + i] = Ex0 - p0;
        out[DISP_OFF + (size_t)b * 3 * Nv + 1 * Nv + i] = Ex1 - p1;
        out[DISP_OFF + (size_t)b * 3 * Nv + 2 * Nv + i] = Ex2 - p2;
        float l0 = src_ml[(size_t)b * 2 * Nv + i];
        float l1 = src_ml[(size_t)b * 2 * Nv + Nv + i];
        float smatch = 1.0f / (1.0f + expf(l1 - l0));
        out[CONF_OFF + ri] = rem * invZ * smatch;
        // ent = -sum p log p = logZ - (sum e*u)/Z,  u = (s - max)/T
        out[ENT_OFF + ri] = logf(rZ) - reu * invZ;
        out[SP_OFF + ri * 3 + 0] = p0;
        out[SP_OFF + ri * 3 + 1] = p1;
        out[SP_OFF + ri * 3 + 2] = p2;
    }
}

extern "C" void kernel_launch(void* const* d_in, const int* in_sizes, int n_in,
                              void* d_out, int out_size) {
    const float* src_can  = (const float*)d_in[0];
    const float* tgt_can  = (const float*)d_in[1];
    const float* src_desc = (const float*)d_in[2];
    const float* tgt_desc = (const float*)d_in[3];
    const float* src_ml   = (const float*)d_in[4];
    const float* tgt_ml   = (const float*)d_in[5];
    const float* src_unc  = (const float*)d_in[6];
    const float* tgt_unc  = (const float*)d_in[7];
    float* out = (float*)d_out;

    prep_kernel<<<(Bv * Cv * Nv + 255) / 256, 256>>>(tgt_desc, tgt_can, tgt_ml, tgt_unc);
    matcher_kernel<<<Bv * Nv, 256>>>(src_can, src_desc, src_ml, src_unc, out);
}